// round 8
// baseline (speedup 1.0000x reference)
#include <cuda_runtime.h>
#include <cstdint>

#define N_ROWS 512
#define D_COLS 256
#define GROUPS 8                 // column groups, 32 cols (128B) each
#define RBLKS  4                 // row-blocks of 128 rows
#define NBLK   (GROUPS * RBLKS)  // 32
#define THREADS 512
#define SCALE_F 16777216.0f      // 2^24 fixed-point scale

// Global state: per-group column stats + tickets + packed scalar.
// Zeroed at module load; finishers reset everything each call (replay-safe).
__device__ float gStats[GROUPS][5][32];
__device__ unsigned int gTick[GROUPS];
__device__ unsigned long long gPacked;

#define SHFL4(v, s) do {                                   \
    (v).x += __shfl_xor_sync(0xFFFFFFFFu, (v).x, (s));     \
    (v).y += __shfl_xor_sync(0xFFFFFFFFu, (v).y, (s));     \
    (v).z += __shfl_xor_sync(0xFFFFFFFFu, (v).z, (s));     \
    (v).w += __shfl_xor_sync(0xFFFFFFFFu, (v).w, (s)); } while (0)

__global__ void __launch_bounds__(THREADS)
club_tile2d(const float* __restrict__ mu,
            const float* __restrict__ logvar,
            const float* __restrict__ h,
            float* __restrict__ out) {
    const int tid  = threadIdx.x;
    const int lane = tid & 31;
    const int w    = tid >> 5;              // warp 0..15
    const int g    = blockIdx.x >> 2;       // column group 0..7
    const int rb   = blockIdx.x & 3;        // row block 0..3
    const int q    = tid & 7;               // col quad 0..7 (4 cols each)
    const int rs   = tid >> 3;              // row slot 0..63

    const float4* __restrict__ h4 = (const float4*)h;
    const float4* __restrict__ m4 = (const float4*)mu;
    const float4* __restrict__ l4 = (const float4*)logvar;

    // ---- Phase 1: 2 rows x float4, dense 128B-line warp accesses ----
    float4 s1 = {0,0,0,0}, s2 = {0,0,0,0}, a = {0,0,0,0},
           b  = {0,0,0,0}, c  = {0,0,0,0};

#define ACC_C(C) {                                          \
        const float iv = __expf(-lv.C);                     \
        s1.C += hv.C;                                       \
        s2.C += hv.C * hv.C;                                \
        a.C  += iv * mv.C;                                  \
        b.C  += iv;                                         \
        c.C  += iv * hv.C * (hv.C - 2.0f * mv.C); }

#pragma unroll
    for (int p = 0; p < 2; ++p) {
        const int row = rb * 128 + rs + p * 64;
        const int i4  = row * (D_COLS / 4) + g * 8 + q;
        const float4 hv = h4[i4];
        const float4 mv = m4[i4];
        const float4 lv = l4[i4];
        ACC_C(x); ACC_C(y); ACC_C(z); ACC_C(w);
    }
#undef ACC_C

    // ---- Phase 2: intra-warp reduce over row slots (lane>>3), keep quad ----
    SHFL4(s1, 8);  SHFL4(s2, 8);  SHFL4(a, 8);  SHFL4(b, 8);  SHFL4(c, 8);
    SHFL4(s1, 16); SHFL4(s2, 16); SHFL4(a, 16); SHFL4(b, 16); SHFL4(c, 16);

    // ---- Phase 3: 16 warps publish per-quad partials; warp 0 combines ----
    __shared__ float4 part[16][5][9];       // padded to dodge bank conflicts
    if (lane < 8) {
        part[w][0][lane] = s1; part[w][1][lane] = s2; part[w][2][lane] = a;
        part[w][3][lane] = b;  part[w][4][lane] = c;
    }
    __syncthreads();
    if (w != 0) return;

    const int q2 = lane & 7;
    const int k  = lane >> 3;               // 0..3
    float4 S1 = {0,0,0,0}, S2 = {0,0,0,0}, A = {0,0,0,0},
           B  = {0,0,0,0}, C  = {0,0,0,0};
#pragma unroll
    for (int j = 0; j < 4; ++j) {
        const int ww = k + 4 * j;
        const float4 v0 = part[ww][0][q2]; S1.x+=v0.x; S1.y+=v0.y; S1.z+=v0.z; S1.w+=v0.w;
        const float4 v1 = part[ww][1][q2]; S2.x+=v1.x; S2.y+=v1.y; S2.z+=v1.z; S2.w+=v1.w;
        const float4 v2 = part[ww][2][q2]; A.x +=v2.x; A.y +=v2.y; A.z +=v2.z; A.w +=v2.w;
        const float4 v3 = part[ww][3][q2]; B.x +=v3.x; B.y +=v3.y; B.z +=v3.z; B.w +=v3.w;
        const float4 v4 = part[ww][4][q2]; C.x +=v4.x; C.y +=v4.y; C.z +=v4.z; C.w +=v4.w;
    }
    SHFL4(S1, 8);  SHFL4(S2, 8);  SHFL4(A, 8);  SHFL4(B, 8);  SHFL4(C, 8);
    SHFL4(S1, 16); SHFL4(S2, 16); SHFL4(A, 16); SHFL4(B, 16); SHFL4(C, 16);

    // ---- Phase 4: ship 20 column-stat floats per lane<8 (fan-in = 4) ----
    if (lane < 8) {
        const int c0 = q2 * 4;
        atomicAdd(&gStats[g][0][c0+0], S1.x); atomicAdd(&gStats[g][0][c0+1], S1.y);
        atomicAdd(&gStats[g][0][c0+2], S1.z); atomicAdd(&gStats[g][0][c0+3], S1.w);
        atomicAdd(&gStats[g][1][c0+0], S2.x); atomicAdd(&gStats[g][1][c0+1], S2.y);
        atomicAdd(&gStats[g][1][c0+2], S2.z); atomicAdd(&gStats[g][1][c0+3], S2.w);
        atomicAdd(&gStats[g][2][c0+0], A.x);  atomicAdd(&gStats[g][2][c0+1], A.y);
        atomicAdd(&gStats[g][2][c0+2], A.z);  atomicAdd(&gStats[g][2][c0+3], A.w);
        atomicAdd(&gStats[g][3][c0+0], B.x);  atomicAdd(&gStats[g][3][c0+1], B.y);
        atomicAdd(&gStats[g][3][c0+2], B.z);  atomicAdd(&gStats[g][3][c0+3], B.w);
        atomicAdd(&gStats[g][4][c0+0], C.x);  atomicAdd(&gStats[g][4][c0+1], C.y);
        atomicAdd(&gStats[g][4][c0+2], C.z);  atomicAdd(&gStats[g][4][c0+3], C.w);
    }
    __syncwarp();

    // ---- Phase 5: group ticket; last row-block combines the group ----
    unsigned int old = 0;
    if (lane == 0)
        asm volatile("atom.acq_rel.gpu.global.add.u32 %0, [%1], %2;"
                     : "=r"(old) : "l"(&gTick[g]), "r"(1u) : "memory");
    old = __shfl_sync(0xFFFFFFFFu, old, 0);
    if (old != RBLKS - 1) return;

    // Acquire above makes the 4 row-blocks' REDGs visible; read via L2.
    const float S1v = __ldcg(&gStats[g][0][lane]);
    const float S2v = __ldcg(&gStats[g][1][lane]);
    const float Av  = __ldcg(&gStats[g][2][lane]);
    const float Bv  = __ldcg(&gStats[g][3][lane]);
    const float Cv  = __ldcg(&gStats[g][4][lane]);

    // Reset group state for the next graph replay.
    gStats[g][0][lane] = 0.f; gStats[g][1][lane] = 0.f;
    gStats[g][2][lane] = 0.f; gStats[g][3][lane] = 0.f;
    gStats[g][4][lane] = 0.f;
    if (lane == 0) gTick[g] = 0u;

    const float invN = 1.0f / (float)N_ROWS;
    float term = Cv + invN * (2.0f * S1v * Av - S2v * Bv);
#pragma unroll
    for (int s = 16; s > 0; s >>= 1)
        term += __shfl_xor_sync(0xFFFFFFFFu, term, s);

    if (lane == 0) {
        // Packed fixed-point atomic: value in bits 6..63, count in bits 0..5.
        const long long fix = __float2ll_rn(term * SCALE_F);
        const unsigned long long myv = ((unsigned long long)fix << 6) + 1ull;
        const unsigned long long prev = atomicAdd(&gPacked, myv);
        if ((prev & 63ull) == (unsigned long long)(GROUPS - 1)) {
            const long long tot = (long long)(prev + myv);
            const long long F   = tot >> 6;          // exact (count=8 < 64)
            out[0]  = (float)((-0.5 / (double)N_ROWS) *
                              ((double)F * (1.0 / (double)SCALE_F)));
            gPacked = 0ull;                          // reset for next replay
        }
    }
}

extern "C" void kernel_launch(void* const* d_in, const int* in_sizes, int n_in,
                              void* d_out, int out_size) {
    const float* mu     = (const float*)d_in[0];
    const float* logvar = (const float*)d_in[1];
    const float* h      = (const float*)d_in[2];
    float* out          = (float*)d_out;
    club_tile2d<<<NBLK, THREADS>>>(mu, logvar, h, out);
}